// round 8
// baseline (speedup 1.0000x reference)
#include <cuda_runtime.h>
#include <cuda_bf16.h>
#include <cstdint>
#include <math_constants.h>

// Problem constants (B=64, T=256, C=1024, H=16, hd=64)
#define BB 64
#define TT 256
#define CC 1024
#define HH 16
#define HD 64
#define MM (BB*TT)   // 16384 rows

// ---------------- static device scratch (no allocation allowed) ----------------
__device__ int8_t g_xq[MM*CC];        // quantized x (int8)
__device__ float  g_xs[MM];           // per-row 1/s  (= clip(max,eps)/127)
__device__ int8_t g_yq[MM*CC];        // quantized attention output
__device__ float  g_ys[MM];
__device__ int8_t g_wq[4][CC*CC];     // ternary weights as int8
__device__ double g_wpart[4][32];     // partial |W| sums
__device__ float  g_ws_s[4];          // s  = 1/clip(mean,eps)
__device__ float  g_ws_inv[4];        // 1/s = clip(mean,eps)
__device__ float  g_q[MM*CC];         // [B,H,T,hd]
__device__ float  g_k[MM*CC];
__device__ float  g_v[MM*CC];
__device__ float  g_y[MM*CC];         // attention out, [B,T,C]

// ---------------- packed f32x2 helpers (attention) ----------------
#define FMA2(d, a, b) asm volatile("fma.rn.f32x2 %0, %1, %2, %0;" : "+l"(d) : "l"(a), "l"(b))
#define MUL2(d, a)    asm volatile("mul.rn.f32x2 %0, %0, %1;"     : "+l"(d) : "l"(a))
__device__ __forceinline__ unsigned long long pack2(float lo, float hi) {
    unsigned long long r;
    asm("mov.b64 %0, {%1, %2};" : "=l"(r) : "f"(lo), "f"(hi));
    return r;
}
__device__ __forceinline__ void unpack2(unsigned long long v, float& lo, float& hi) {
    asm("mov.b64 {%0, %1}, %2;" : "=f"(lo), "=f"(hi) : "l"(v));
}

// ---------------- cp.async helpers ----------------
__device__ __forceinline__ void cpasync16(void* smem_ptr, const void* gmem_ptr) {
    uint32_t s = (uint32_t)__cvta_generic_to_shared(smem_ptr);
    asm volatile("cp.async.cg.shared.global [%0], [%1], 16;\n" :: "r"(s), "l"(gmem_ptr));
}
#define CP_COMMIT() asm volatile("cp.async.commit_group;\n")
#define CP_WAIT(N)  asm volatile("cp.async.wait_group %0;\n" :: "n"(N))

// ---------------- weight abs-sum (deterministic, fp64) ----------------
__global__ __launch_bounds__(256) void wsum_kernel(const float* __restrict__ w0,
                                                   const float* __restrict__ w1,
                                                   const float* __restrict__ w2,
                                                   const float* __restrict__ w3)
{
    const float* w = (blockIdx.y == 0) ? w0 : (blockIdx.y == 1) ? w1
                   : (blockIdx.y == 2) ? w2 : w3;
    int base = blockIdx.x * 32768;
    const float4* w4 = (const float4*)(w + base);
    double s = 0.0;
    for (int i = threadIdx.x; i < 8192; i += 256) {
        float4 v = w4[i];
        s += (double)(fabsf(v.x) + fabsf(v.y) + fabsf(v.z) + fabsf(v.w));
    }
    __shared__ double ds[256];
    ds[threadIdx.x] = s;
    __syncthreads();
    for (int st = 128; st; st >>= 1) {
        if (threadIdx.x < st) ds[threadIdx.x] += ds[threadIdx.x + st];
        __syncthreads();
    }
    if (threadIdx.x == 0) g_wpart[blockIdx.y][blockIdx.x] = ds[0];
}

__global__ void wscale_kernel()
{
    int i = threadIdx.x;
    if (i < 4) {
        double s = 0.0;
        for (int j = 0; j < 32; j++) s += g_wpart[i][j];
        float mean = (float)(s / (double)(CC * CC));
        float mc = fmaxf(mean, 1e-5f);
        g_ws_s[i]   = 1.0f / mc;
        g_ws_inv[i] = mc;
    }
}

// ---------------- ternary weight quantization -> int8 (all 4 weights) ----------------
__global__ __launch_bounds__(256) void wquant_kernel(const float* __restrict__ w0,
                                                     const float* __restrict__ w1,
                                                     const float* __restrict__ w2,
                                                     const float* __restrict__ w3)
{
    int idx = blockIdx.y;
    const float* src = (idx == 0) ? w0 : (idx == 1) ? w1 : (idx == 2) ? w2 : w3;
    float s = g_ws_s[idx];
    int gid = blockIdx.x * 256 + threadIdx.x;        // 1024 blocks -> 262144 float4
    float4 v = ((const float4*)src)[gid];
    char4 o;
    o.x = (char)(int)fminf(fmaxf(rintf(v.x * s), -1.f), 1.f);
    o.y = (char)(int)fminf(fmaxf(rintf(v.y * s), -1.f), 1.f);
    o.z = (char)(int)fminf(fmaxf(rintf(v.z * s), -1.f), 1.f);
    o.w = (char)(int)fminf(fmaxf(rintf(v.w * s), -1.f), 1.f);
    ((char4*)g_wq[idx])[gid] = o;
}

// ---------------- per-token int8 activation quantization ----------------
__global__ __launch_bounds__(256) void actquant_kernel(const float* __restrict__ xin, int sel)
{
    const float* src  = sel ? (const float*)g_y : xin;
    int8_t* outq      = sel ? g_yq : g_xq;
    float* sinv       = sel ? g_ys : g_xs;

    int row = blockIdx.x;
    int tid = threadIdx.x;
    const float4* r4 = (const float4*)(src + (size_t)row * CC);
    float4 v = r4[tid];
    float mx = fmaxf(fmaxf(fabsf(v.x), fabsf(v.y)), fmaxf(fabsf(v.z), fabsf(v.w)));
    for (int o = 16; o; o >>= 1) mx = fmaxf(mx, __shfl_xor_sync(0xffffffffu, mx, o));
    __shared__ float wmax[8];
    if ((tid & 31) == 0) wmax[tid >> 5] = mx;
    __syncthreads();
    float am = wmax[0];
    #pragma unroll
    for (int i = 1; i < 8; i++) am = fmaxf(am, wmax[i]);
    float mc = fmaxf(am, 1e-5f);
    float s = 127.0f / mc;

    char4 o;
    o.x = (char)(int)fminf(fmaxf(rintf(v.x * s), -128.f), 127.f);
    o.y = (char)(int)fminf(fmaxf(rintf(v.y * s), -128.f), 127.f);
    o.z = (char)(int)fminf(fmaxf(rintf(v.z * s), -128.f), 127.f);
    o.w = (char)(int)fminf(fmaxf(rintf(v.w * s), -128.f), 127.f);
    ((char4*)(outq + (size_t)row * CC))[tid] = o;
    if (tid == 0) sinv[row] = mc / 127.0f;
}

// ---------------- int8 IMMA GEMM:  OUT[m,n] = (A[m,:] . W[n,:]) * sA[m] * sW ----------------
__device__ __forceinline__ void mma_s8(int* c, const uint32_t* a, uint32_t b0, uint32_t b1)
{
    asm volatile(
        "mma.sync.aligned.m16n8k32.row.col.s32.s8.s8.s32 "
        "{%0,%1,%2,%3}, {%4,%5,%6,%7}, {%8,%9}, {%0,%1,%2,%3};\n"
        : "+r"(c[0]), "+r"(c[1]), "+r"(c[2]), "+r"(c[3])
        : "r"(a[0]), "r"(a[1]), "r"(a[2]), "r"(a[3]), "r"(b0), "r"(b1));
}

#define BM 128
#define BN 128
#define BKB 64          // K bytes per stage (= 64 int8)
#define NSTG 3          // cp.async pipeline depth
#define RST 80          // smem row stride bytes (64 + 16 pad) -> conflict-free
#define STAGE_BYTES (BM * RST)                 // 10240 per matrix
#define GEMM_SMEM (2 * NSTG * STAGE_BYTES)     // 61440 bytes

__global__ __launch_bounds__(256) void gemm_kernel(int qkv, int w_idx_p, int mode_p,
                                                   float* __restrict__ dst,
                                                   const float* __restrict__ bias)
{
    extern __shared__ __align__(16) char smem[];
    char* As = smem;                          // [NSTG][128*80]
    char* Bs = smem + NSTG * STAGE_BYTES;     // [NSTG][128*80]

    int w_idx = qkv ? (int)blockIdx.z : w_idx_p;
    int mode  = qkv ? (int)blockIdx.z : mode_p;

    const int8_t* __restrict__ A  = qkv ? g_xq : g_yq;
    const float* __restrict__ sA  = qkv ? g_xs : g_ys;
    const int8_t* __restrict__ W  = g_wq[w_idx];

    int m0 = blockIdx.x * BM;
    int n0 = blockIdx.y * BN;
    int tid = threadIdx.x;
    int warp = tid >> 5, lane = tid & 31;
    int wm = warp >> 1, wn = warp & 1;     // 4x2 warp grid, warp tile 32x64
    int g = lane >> 2, tg = lane & 3;

    int acc[2][8][4];
    #pragma unroll
    for (int i = 0; i < 2; i++)
        #pragma unroll
        for (int j = 0; j < 8; j++)
            #pragma unroll
            for (int r = 0; r < 4; r++) acc[i][j][r] = 0;

    // stage loader: per matrix 128 rows x 64B = 512 x 16B chunks; 2 per thread per matrix
    auto load_stage = [&](int st, int kk) {
        #pragma unroll
        for (int i = 0; i < 2; i++) {
            int idx = tid + i * 256;               // 0..511
            int r = idx >> 2, c = (idx & 3) * 16;  // byte col 0..48
            cpasync16(&As[st * STAGE_BYTES + r * RST + c],
                      A + (size_t)(m0 + r) * CC + kk + c);
            cpasync16(&Bs[st * STAGE_BYTES + r * RST + c],
                      W + (size_t)(n0 + r) * CC + kk + c);
        }
    };

    load_stage(0, 0);
    CP_COMMIT();
    load_stage(1, BKB);
    CP_COMMIT();

    const int NT = CC / BKB;   // 16 stages
    for (int t = 0; t < NT; t++) {
        if (t + 2 < NT) {
            load_stage((t + 2) % NSTG, (t + 2) * BKB);
            CP_COMMIT();
            CP_WAIT(2);          // stage t resident
        } else {
            CP_WAIT(0);
        }
        __syncthreads();

        const char* Ab = &As[(t % NSTG) * STAGE_BYTES];
        const char* Bb = &Bs[(t % NSTG) * STAGE_BYTES];
        #pragma unroll
        for (int ks = 0; ks < 2; ks++) {           // 2 x K32 per stage
            int kb = ks * 32;
            uint32_t a[2][4];
            #pragma unroll
            for (int i = 0; i < 2; i++) {
                int row = wm * 32 + i * 16;
                a[i][0] = *(const uint32_t*)&Ab[(row +     g) * RST + kb + tg * 4];
                a[i][1] = *(const uint32_t*)&Ab[(row + 8 + g) * RST + kb + tg * 4];
                a[i][2] = *(const uint32_t*)&Ab[(row +     g) * RST + kb + tg * 4 + 16];
                a[i][3] = *(const uint32_t*)&Ab[(row + 8 + g) * RST + kb + tg * 4 + 16];
            }
            #pragma unroll
            for (int j = 0; j < 8; j++) {
                int n = wn * 64 + j * 8 + g;
                uint32_t b0 = *(const uint32_t*)&Bb[n * RST + kb + tg * 4];
                uint32_t b1 = *(const uint32_t*)&Bb[n * RST + kb + tg * 4 + 16];
                mma_s8(acc[0][j], a[0], b0, b1);
                mma_s8(acc[1][j], a[1], b0, b1);
            }
        }
        __syncthreads();
    }

    // epilogue: exact s32 -> f32, scale + write
    float sw = g_ws_inv[w_idx];
    float* sc = (mode == 0) ? g_q : (mode == 1) ? g_k : g_v;   // scatter targets
    #pragma unroll
    for (int i = 0; i < 2; i++) {
        int r0 = m0 + wm * 32 + i * 16 + g;
        float s0 = sA[r0] * sw;
        float s1 = sA[r0 + 8] * sw;
        #pragma unroll
        for (int j = 0; j < 8; j++) {
            int c = n0 + wn * 64 + j * 8 + tg * 2;
            float v00 = (float)acc[i][j][0] * s0, v01 = (float)acc[i][j][1] * s0;
            float v10 = (float)acc[i][j][2] * s1, v11 = (float)acc[i][j][3] * s1;
            if (mode == 3) {
                float b0 = bias[c], b1 = bias[c + 1];
                float2* p0 = (float2*)&dst[(size_t)r0 * CC + c];
                float2* p1 = (float2*)&dst[(size_t)(r0 + 8) * CC + c];
                *p0 = make_float2(v00 + b0, v01 + b1);
                *p1 = make_float2(v10 + b0, v11 + b1);
            } else {
                int h = c >> 6, d = c & 63;
                {
                    int m = r0, t2 = m & (TT - 1), b = m >> 8;
                    float2* p = (float2*)&sc[(((b * HH + h) * TT + t2) * HD) + d];
                    *p = make_float2(v00, v01);
                }
                {
                    int m = r0 + 8, t2 = m & (TT - 1), b = m >> 8;
                    float2* p = (float2*)&sc[(((b * HH + h) * TT + t2) * HD) + d];
                    *p = make_float2(v10, v11);
                }
            }
        }
    }
}

// ---------------- fused causal attention, one (b,h) per CTA, packed f32x2 math ----------------
// smem: K tile [256][64] + V tile [256][64] fp32 = 131072 B (dynamic)
__global__ __launch_bounds__(256) void attn_kernel()
{
    extern __shared__ float sm[];
    float* Ks = sm;
    float* Vs = sm + TT * HD;

    int bh = blockIdx.x;               // 0..1023
    size_t base = (size_t)bh * (TT * HD);
    int tid = threadIdx.x;             // = query row t

    const float4* k4 = (const float4*)(g_k + base);
    const float4* v4 = (const float4*)(g_v + base);
    float4* Ks4 = (float4*)Ks;
    float4* Vs4 = (float4*)Vs;
    #pragma unroll
    for (int i = tid; i < TT * HD / 4; i += 256) {
        Ks4[i] = k4[i];
        Vs4[i] = v4[i];
    }

    unsigned long long q2[32];
    const ulonglong2* qg = (const ulonglong2*)(g_q + base + (size_t)tid * HD);
    #pragma unroll
    for (int i = 0; i < 16; i++) {
        ulonglong2 u = qg[i];
        q2[2 * i] = u.x; q2[2 * i + 1] = u.y;
    }
    __syncthreads();

    float m = -CUDART_INF_F, l = 0.f;
    unsigned long long o2[32];
    #pragma unroll
    for (int i = 0; i < 32; i++) o2[i] = 0ULL;

    for (int j = 0; j <= tid; j++) {
        const ulonglong2* kj = (const ulonglong2*)(Ks + j * HD);   // warp-broadcast
        unsigned long long acc[4] = {0ULL, 0ULL, 0ULL, 0ULL};
        #pragma unroll
        for (int c = 0; c < 16; c++) {
            ulonglong2 kv = kj[c];
            FMA2(acc[c & 3], q2[2 * c],     kv.x);
            FMA2(acc[c & 3], q2[2 * c + 1], kv.y);
        }
        float a0, a1, b0, b1, c0, c1, d0, d1;
        unpack2(acc[0], a0, a1); unpack2(acc[1], b0, b1);
        unpack2(acc[2], c0, c1); unpack2(acc[3], d0, d1);
        float s = (((a0 + a1) + (b0 + b1)) + ((c0 + c1) + (d0 + d1))) * 0.125f; // 1/sqrt(64)

        float p;
        if (s <= m) {
            p = __expf(s - m);
        } else {
            float corr = __expf(m - s);               // exp(-inf)=0 on first iter
            l *= corr;
            unsigned long long corr2 = pack2(corr, corr);
            #pragma unroll
            for (int i = 0; i < 32; i++) MUL2(o2[i], corr2);
            m = s;
            p = 1.f;
        }
        l += p;
        unsigned long long p2 = pack2(p, p);
        const ulonglong2* vj = (const ulonglong2*)(Vs + j * HD);  // warp-broadcast
        #pragma unroll
        for (int c = 0; c < 16; c++) {
            ulonglong2 vv = vj[c];
            FMA2(o2[2 * c],     p2, vv.x);
            FMA2(o2[2 * c + 1], p2, vv.y);
        }
    }

    float inv = 1.0f / l;
    unsigned long long inv2 = pack2(inv, inv);
    int b = bh >> 4, h = bh & (HH - 1);
    unsigned long long* yout =
        (unsigned long long*)(g_y + ((size_t)(b * TT + tid)) * CC + h * HD);
    #pragma unroll
    for (int c = 0; c < 32; c++) {
        MUL2(o2[c], inv2);
        yout[c] = o2[c];
    }
}

// ---------------- launch ----------------
extern "C" void kernel_launch(void* const* d_in, const int* in_sizes, int n_in,
                              void* d_out, int out_size)
{
    const float* x  = (const float*)d_in[0];
    const float* Wq = (const float*)d_in[1];
    const float* Wk = (const float*)d_in[2];
    const float* Wv = (const float*)d_in[3];
    const float* Wp = (const float*)d_in[4];
    const float* bp = (const float*)d_in[5];
    float* out = (float*)d_out;

    cudaFuncSetAttribute(gemm_kernel, cudaFuncAttributeMaxDynamicSharedMemorySize, GEMM_SMEM);
    cudaFuncSetAttribute(attn_kernel, cudaFuncAttributeMaxDynamicSharedMemorySize, 131072);

    // 1) weight scales (deterministic fp64 two-pass)
    wsum_kernel<<<dim3(32, 4), 256>>>(Wq, Wk, Wv, Wp);
    wscale_kernel<<<1, 32>>>();

    // 2) ternary-quantize all 4 weights to int8 (one launch)
    wquant_kernel<<<dim3(1024, 4), 256>>>(Wq, Wk, Wv, Wp);

    // 3) per-token quantize x to int8
    actquant_kernel<<<MM, 256>>>(x, 0);

    // 4) Q/K/V projections fused in one launch (exact int8 IMMA), scatter to [B,H,T,hd]
    gemm_kernel<<<dim3(MM / BM, CC / BN, 3), 256, GEMM_SMEM>>>(1, 0, 0, nullptr, nullptr);

    // 5) fused causal attention
    attn_kernel<<<BB * HH, 256, 131072>>>();

    // 6) quantize attention output to int8
    actquant_kernel<<<MM, 256>>>(nullptr, 1);

    // 7) output projection (+bias) straight into d_out
    gemm_kernel<<<dim3(MM / BM, CC / BN, 1), 256, GEMM_SMEM>>>(0, 3, 3, out, bp);
}

// round 10
// speedup vs baseline: 1.6440x; 1.6440x over previous
#include <cuda_runtime.h>
#include <cuda_bf16.h>
#include <cstdint>
#include <math_constants.h>

// Problem constants (B=64, T=256, C=1024, H=16, hd=64)
#define BB 64
#define TT 256
#define CC 1024
#define HH 16
#define HD 64
#define MM (BB*TT)   // 16384 rows

// ---------------- static device scratch (no allocation allowed) ----------------
__device__ __nv_bfloat16 g_xq[MM*CC];        // quantized x (int values as bf16)
__device__ float         g_xs[MM];           // per-row 1/s  (= clip(max,eps)/127)
__device__ __nv_bfloat16 g_yq[MM*CC];        // quantized attention output
__device__ float         g_ys[MM];
__device__ __nv_bfloat16 g_wq[4][CC*CC];     // ternary weights as bf16
__device__ double        g_wpart[4][32];     // partial |W| sums
__device__ float         g_ws_s[4];          // s  = 1/clip(mean,eps)
__device__ float         g_ws_inv[4];        // 1/s = clip(mean,eps)
__device__ float         g_q[MM*CC];         // [B,H,T,hd]
__device__ float         g_k[MM*CC];
__device__ float         g_v[MM*CC];
__device__ float         g_y[MM*CC];         // attention out, [B,T,C]

// ---------------- packed f32x2 helpers (attention) ----------------
#define FMA2(d, a, b) asm volatile("fma.rn.f32x2 %0, %1, %2, %0;" : "+l"(d) : "l"(a), "l"(b))
#define MUL2(d, a)    asm volatile("mul.rn.f32x2 %0, %0, %1;"     : "+l"(d) : "l"(a))
__device__ __forceinline__ unsigned long long pack2(float lo, float hi) {
    unsigned long long r;
    asm("mov.b64 %0, {%1, %2};" : "=l"(r) : "f"(lo), "f"(hi));
    return r;
}
__device__ __forceinline__ void unpack2(unsigned long long v, float& lo, float& hi) {
    asm("mov.b64 {%0, %1}, %2;" : "=f"(lo), "=f"(hi) : "l"(v));
}

// ---------------- cp.async helpers ----------------
__device__ __forceinline__ void cpasync16(void* smem_ptr, const void* gmem_ptr) {
    uint32_t s = (uint32_t)__cvta_generic_to_shared(smem_ptr);
    asm volatile("cp.async.cg.shared.global [%0], [%1], 16;\n" :: "r"(s), "l"(gmem_ptr));
}
#define CP_COMMIT() asm volatile("cp.async.commit_group;\n")
#define CP_WAIT(N)  asm volatile("cp.async.wait_group %0;\n" :: "n"(N))

// ---------------- weight abs-sum (deterministic, fp64) ----------------
__global__ __launch_bounds__(256) void wsum_kernel(const float* __restrict__ w0,
                                                   const float* __restrict__ w1,
                                                   const float* __restrict__ w2,
                                                   const float* __restrict__ w3)
{
    const float* w = (blockIdx.y == 0) ? w0 : (blockIdx.y == 1) ? w1
                   : (blockIdx.y == 2) ? w2 : w3;
    int base = blockIdx.x * 32768;
    const float4* w4 = (const float4*)(w + base);
    double s = 0.0;
    for (int i = threadIdx.x; i < 8192; i += 256) {
        float4 v = w4[i];
        s += (double)(fabsf(v.x) + fabsf(v.y) + fabsf(v.z) + fabsf(v.w));
    }
    __shared__ double ds[256];
    ds[threadIdx.x] = s;
    __syncthreads();
    for (int st = 128; st; st >>= 1) {
        if (threadIdx.x < st) ds[threadIdx.x] += ds[threadIdx.x + st];
        __syncthreads();
    }
    if (threadIdx.x == 0) g_wpart[blockIdx.y][blockIdx.x] = ds[0];
}

__global__ void wscale_kernel()
{
    int i = threadIdx.x;
    if (i < 4) {
        double s = 0.0;
        for (int j = 0; j < 32; j++) s += g_wpart[i][j];
        float mean = (float)(s / (double)(CC * CC));
        float mc = fmaxf(mean, 1e-5f);
        g_ws_s[i]   = 1.0f / mc;
        g_ws_inv[i] = mc;
    }
}

// ---------------- ternary weight quantization -> bf16 (all 4 weights) ----------------
__global__ __launch_bounds__(256) void wquant_kernel(const float* __restrict__ w0,
                                                     const float* __restrict__ w1,
                                                     const float* __restrict__ w2,
                                                     const float* __restrict__ w3)
{
    int idx = blockIdx.y;
    const float* src = (idx == 0) ? w0 : (idx == 1) ? w1 : (idx == 2) ? w2 : w3;
    float s = g_ws_s[idx];
    int gid = blockIdx.x * 256 + threadIdx.x;        // 1024 blocks -> 262144 float4
    float4 v = ((const float4*)src)[gid];
    float a = fminf(fmaxf(rintf(v.x * s), -1.f), 1.f);
    float b = fminf(fmaxf(rintf(v.y * s), -1.f), 1.f);
    float c = fminf(fmaxf(rintf(v.z * s), -1.f), 1.f);
    float d = fminf(fmaxf(rintf(v.w * s), -1.f), 1.f);
    __nv_bfloat162* out = (__nv_bfloat162*)g_wq[idx];
    out[gid * 2 + 0] = __floats2bfloat162_rn(a, b);
    out[gid * 2 + 1] = __floats2bfloat162_rn(c, d);
}

// ---------------- per-token int8 activation quantization -> bf16 ----------------
__global__ __launch_bounds__(256) void actquant_kernel(const float* __restrict__ xin, int sel)
{
    const float* src      = sel ? (const float*)g_y : xin;
    __nv_bfloat16* outq   = sel ? g_yq : g_xq;
    float* sinv           = sel ? g_ys : g_xs;

    int row = blockIdx.x;
    int tid = threadIdx.x;
    const float4* r4 = (const float4*)(src + (size_t)row * CC);
    float4 v = r4[tid];
    float mx = fmaxf(fmaxf(fabsf(v.x), fabsf(v.y)), fmaxf(fabsf(v.z), fabsf(v.w)));
    for (int o = 16; o; o >>= 1) mx = fmaxf(mx, __shfl_xor_sync(0xffffffffu, mx, o));
    __shared__ float wmax[8];
    if ((tid & 31) == 0) wmax[tid >> 5] = mx;
    __syncthreads();
    float am = wmax[0];
    #pragma unroll
    for (int i = 1; i < 8; i++) am = fmaxf(am, wmax[i]);
    float mc = fmaxf(am, 1e-5f);
    float s = 127.0f / mc;

    float a = fminf(fmaxf(rintf(v.x * s), -128.f), 127.f);
    float b = fminf(fmaxf(rintf(v.y * s), -128.f), 127.f);
    float c = fminf(fmaxf(rintf(v.z * s), -128.f), 127.f);
    float d = fminf(fmaxf(rintf(v.w * s), -128.f), 127.f);
    __nv_bfloat162* o2 = (__nv_bfloat162*)(outq + (size_t)row * CC);
    o2[tid * 2 + 0] = __floats2bfloat162_rn(a, b);
    o2[tid * 2 + 1] = __floats2bfloat162_rn(c, d);
    if (tid == 0) sinv[row] = mc / 127.0f;
}

// ---------------- bf16 MMA GEMM: ldmatrix + 3-stage cp.async, single sync/stage ----------------
__device__ __forceinline__ void mma16816(float* c, const uint32_t* a, uint32_t b0, uint32_t b1)
{
    asm volatile(
        "mma.sync.aligned.m16n8k16.row.col.f32.bf16.bf16.f32 "
        "{%0,%1,%2,%3}, {%4,%5,%6,%7}, {%8,%9}, {%0,%1,%2,%3};\n"
        : "+f"(c[0]), "+f"(c[1]), "+f"(c[2]), "+f"(c[3])
        : "r"(a[0]), "r"(a[1]), "r"(a[2]), "r"(a[3]), "r"(b0), "r"(b1));
}
__device__ __forceinline__ void ldsm_x4(uint32_t* r, uint32_t addr)
{
    asm volatile("ldmatrix.sync.aligned.m8n8.x4.shared.b16 {%0,%1,%2,%3}, [%4];"
                 : "=r"(r[0]), "=r"(r[1]), "=r"(r[2]), "=r"(r[3]) : "r"(addr));
}

#define BM 128
#define BN 128
#define BK 64
#define NSTG 3
#define AST 72                                  // smem row stride in halves (144 B)
#define STAGE_HALVES (BM * AST)                 // per matrix per stage
#define GEMM_SMEM (NSTG * 2 * STAGE_HALVES * 2) // 110592 bytes

__global__ __launch_bounds__(256, 2) void gemm_kernel(int qkv, int w_idx_p, int mode_p,
                                                      float* __restrict__ dst,
                                                      const float* __restrict__ bias)
{
    extern __shared__ __align__(16) __nv_bfloat16 smem[];
    __nv_bfloat16* As = smem;                       // [NSTG][BM*AST]
    __nv_bfloat16* Bs = smem + NSTG * STAGE_HALVES; // [NSTG][BN*AST]

    int w_idx = qkv ? (int)blockIdx.z : w_idx_p;
    int mode  = qkv ? (int)blockIdx.z : mode_p;

    const __nv_bfloat16* __restrict__ A  = qkv ? g_xq : g_yq;
    const float* __restrict__ sA         = qkv ? g_xs : g_ys;
    const __nv_bfloat16* __restrict__ W  = g_wq[w_idx];

    int m0 = blockIdx.x * BM;
    int n0 = blockIdx.y * BN;
    int tid = threadIdx.x;
    int warp = tid >> 5, lane = tid & 31;
    int wm = warp >> 1, wn = warp & 1;     // 4x2 warp grid, warp tile 32x64
    int g = lane >> 2, tg = lane & 3;

    // ldmatrix per-lane source rows/cols (halves)
    uint32_t sAu = (uint32_t)__cvta_generic_to_shared(As);
    uint32_t sBu = (uint32_t)__cvta_generic_to_shared(Bs);
    int a_row = wm * 32 + (lane & 15);
    int a_col = (lane >> 4) * 8;
    int b_row = wn * 64 + ((lane >> 4) << 3) + (lane & 7);
    int b_col = ((lane >> 3) & 1) * 8;

    float acc[2][8][4];
    #pragma unroll
    for (int i = 0; i < 2; i++)
        #pragma unroll
        for (int j = 0; j < 8; j++)
            #pragma unroll
            for (int r = 0; r < 4; r++) acc[i][j][r] = 0.f;

    // stage loader: per matrix 1024 x 16B chunks, 8 cp.async per thread
    auto load_stage = [&](int st, int kk) {
        #pragma unroll
        for (int i = 0; i < 4; i++) {
            int idx = tid + i * 256;             // 0..1023
            int r = idx >> 3, c4 = (idx & 7) * 8; // halves 0..56
            cpasync16(&As[st * STAGE_HALVES + r * AST + c4],
                      &A[(size_t)(m0 + r) * CC + kk + c4]);
            cpasync16(&Bs[st * STAGE_HALVES + r * AST + c4],
                      &W[(size_t)(n0 + r) * CC + kk + c4]);
        }
    };

    load_stage(0, 0);
    CP_COMMIT();
    load_stage(1, BK);
    CP_COMMIT();

    const int NT = CC / BK;   // 16
    for (int t = 0; t < NT; t++) {
        if (t < NT - 1) { CP_WAIT(1); } else { CP_WAIT(0); }
        __syncthreads();

        uint32_t Ab = sAu + (uint32_t)((t % NSTG) * STAGE_HALVES) * 2;
        uint32_t Bb = sBu + (uint32_t)((t % NSTG) * STAGE_HALVES) * 2;
        #pragma unroll
        for (int ks = 0; ks < BK; ks += 16) {
            uint32_t a[2][4];
            ldsm_x4(a[0], Ab + (uint32_t)((a_row)      * AST + ks + a_col) * 2);
            ldsm_x4(a[1], Ab + (uint32_t)((a_row + 16) * AST + ks + a_col) * 2);
            #pragma unroll
            for (int j2 = 0; j2 < 4; j2++) {
                uint32_t b[4];
                ldsm_x4(b, Bb + (uint32_t)((b_row + j2 * 16) * AST + ks + b_col) * 2);
                mma16816(acc[0][2 * j2],     a[0], b[0], b[1]);
                mma16816(acc[1][2 * j2],     a[1], b[0], b[1]);
                mma16816(acc[0][2 * j2 + 1], a[0], b[2], b[3]);
                mma16816(acc[1][2 * j2 + 1], a[1], b[2], b[3]);
            }
        }

        if (t + 2 < NT) {
            load_stage((t + 2) % NSTG, (t + 2) * BK);
            CP_COMMIT();
        }
    }

    // epilogue: scale + write
    float sw = g_ws_inv[w_idx];
    float* sc = (mode == 0) ? g_q : (mode == 1) ? g_k : g_v;   // scatter targets
    #pragma unroll
    for (int i = 0; i < 2; i++) {
        int r0 = m0 + wm * 32 + i * 16 + g;
        float s0 = sA[r0] * sw;
        float s1 = sA[r0 + 8] * sw;
        #pragma unroll
        for (int j = 0; j < 8; j++) {
            int c = n0 + wn * 64 + j * 8 + tg * 2;
            float v00 = acc[i][j][0] * s0, v01 = acc[i][j][1] * s0;
            float v10 = acc[i][j][2] * s1, v11 = acc[i][j][3] * s1;
            if (mode == 3) {
                float b0 = bias[c], b1 = bias[c + 1];
                float2* p0 = (float2*)&dst[(size_t)r0 * CC + c];
                float2* p1 = (float2*)&dst[(size_t)(r0 + 8) * CC + c];
                *p0 = make_float2(v00 + b0, v01 + b1);
                *p1 = make_float2(v10 + b0, v11 + b1);
            } else {
                int h = c >> 6, d = c & 63;
                {
                    int m = r0, t2 = m & (TT - 1), b = m >> 8;
                    float2* p = (float2*)&sc[(((b * HH + h) * TT + t2) * HD) + d];
                    *p = make_float2(v00, v01);
                }
                {
                    int m = r0 + 8, t2 = m & (TT - 1), b = m >> 8;
                    float2* p = (float2*)&sc[(((b * HH + h) * TT + t2) * HD) + d];
                    *p = make_float2(v10, v11);
                }
            }
        }
    }
}

// ---------------- fused causal attention, one (b,h) per CTA, packed f32x2 math ----------------
// smem: K tile [256][64] + V tile [256][64] fp32 = 131072 B (dynamic)
__global__ __launch_bounds__(256) void attn_kernel()
{
    extern __shared__ float sm[];
    float* Ks = sm;
    float* Vs = sm + TT * HD;

    int bh = blockIdx.x;               // 0..1023
    size_t base = (size_t)bh * (TT * HD);
    int tid = threadIdx.x;             // = query row t

    const float4* k4 = (const float4*)(g_k + base);
    const float4* v4 = (const float4*)(g_v + base);
    float4* Ks4 = (float4*)Ks;
    float4* Vs4 = (float4*)Vs;
    #pragma unroll
    for (int i = tid; i < TT * HD / 4; i += 256) {
        Ks4[i] = k4[i];
        Vs4[i] = v4[i];
    }

    unsigned long long q2[32];
    const ulonglong2* qg = (const ulonglong2*)(g_q + base + (size_t)tid * HD);
    #pragma unroll
    for (int i = 0; i < 16; i++) {
        ulonglong2 u = qg[i];
        q2[2 * i] = u.x; q2[2 * i + 1] = u.y;
    }
    __syncthreads();

    float m = -CUDART_INF_F, l = 0.f;
    unsigned long long o2[32];
    #pragma unroll
    for (int i = 0; i < 32; i++) o2[i] = 0ULL;

    for (int j = 0; j <= tid; j++) {
        const ulonglong2* kj = (const ulonglong2*)(Ks + j * HD);   // warp-broadcast
        unsigned long long acc[4] = {0ULL, 0ULL, 0ULL, 0ULL};
        #pragma unroll
        for (int c = 0; c < 16; c++) {
            ulonglong2 kv = kj[c];
            FMA2(acc[c & 3], q2[2 * c],     kv.x);
            FMA2(acc[c & 3], q2[2 * c + 1], kv.y);
        }
        float a0, a1, b0, b1, c0, c1, d0, d1;
        unpack2(acc[0], a0, a1); unpack2(acc[1], b0, b1);
        unpack2(acc[2], c0, c1); unpack2(acc[3], d0, d1);
        float s = (((a0 + a1) + (b0 + b1)) + ((c0 + c1) + (d0 + d1))) * 0.125f; // 1/sqrt(64)

        float p;
        if (s <= m) {
            p = __expf(s - m);
        } else {
            float corr = __expf(m - s);               // exp(-inf)=0 on first iter
            l *= corr;
            unsigned long long corr2 = pack2(corr, corr);
            #pragma unroll
            for (int i = 0; i < 32; i++) MUL2(o2[i], corr2);
            m = s;
            p = 1.f;
        }
        l += p;
        unsigned long long p2 = pack2(p, p);
        const ulonglong2* vj = (const ulonglong2*)(Vs + j * HD);  // warp-broadcast
        #pragma unroll
        for (int c = 0; c < 16; c++) {
            ulonglong2 vv = vj[c];
            FMA2(o2[2 * c],     p2, vv.x);
            FMA2(o2[2 * c + 1], p2, vv.y);
        }
    }

    float inv = 1.0f / l;
    unsigned long long inv2 = pack2(inv, inv);
    int b = bh >> 4, h = bh & (HH - 1);
    unsigned long long* yout =
        (unsigned long long*)(g_y + ((size_t)(b * TT + tid)) * CC + h * HD);
    #pragma unroll
    for (int c = 0; c < 32; c++) {
        MUL2(o2[c], inv2);
        yout[c] = o2[c];
    }
}

// ---------------- launch ----------------
extern "C" void kernel_launch(void* const* d_in, const int* in_sizes, int n_in,
                              void* d_out, int out_size)
{
    const float* x  = (const float*)d_in[0];
    const float* Wq = (const float*)d_in[1];
    const float* Wk = (const float*)d_in[2];
    const float* Wv = (const float*)d_in[3];
    const float* Wp = (const float*)d_in[4];
    const float* bp = (const float*)d_in[5];
    float* out = (float*)d_out;

    cudaFuncSetAttribute(gemm_kernel, cudaFuncAttributeMaxDynamicSharedMemorySize, GEMM_SMEM);
    cudaFuncSetAttribute(attn_kernel, cudaFuncAttributeMaxDynamicSharedMemorySize, 131072);

    // 1) weight scales (deterministic fp64 two-pass)
    wsum_kernel<<<dim3(32, 4), 256>>>(Wq, Wk, Wv, Wp);
    wscale_kernel<<<1, 32>>>();

    // 2) ternary-quantize all 4 weights to bf16 (one launch)
    wquant_kernel<<<dim3(1024, 4), 256>>>(Wq, Wk, Wv, Wp);

    // 3) per-token quantize x
    actquant_kernel<<<MM, 256>>>(x, 0);

    // 4) Q/K/V projections fused in one launch (exact integer MMA), scatter to [B,H,T,hd]
    gemm_kernel<<<dim3(MM / BM, CC / BN, 3), 256, GEMM_SMEM>>>(1, 0, 0, nullptr, nullptr);

    // 5) fused causal attention
    attn_kernel<<<BB * HH, 256, 131072>>>();

    // 6) quantize attention output
    actquant_kernel<<<MM, 256>>>(nullptr, 1);

    // 7) output projection (+bias) straight into d_out
    gemm_kernel<<<dim3(MM / BM, CC / BN, 1), 256, GEMM_SMEM>>>(0, 3, 3, out, bp);
}

// round 13
// speedup vs baseline: 1.7033x; 1.0360x over previous
#include <cuda_runtime.h>
#include <cuda_bf16.h>
#include <cstdint>
#include <math_constants.h>

// Problem constants (B=64, T=256, C=1024, H=16, hd=64)
#define BB 64
#define TT 256
#define CC 1024
#define HH 16
#define HD 64
#define MM (BB*TT)   // 16384 rows

// ---------------- static device scratch (no allocation allowed) ----------------
__device__ __nv_bfloat16 g_xq[MM*CC];        // quantized x (int values as bf16)
__device__ float         g_xs[MM];           // per-row 1/s  (= clip(max,eps)/127)
__device__ __nv_bfloat16 g_yq[MM*CC];        // quantized attention output
__device__ float         g_ys[MM];
__device__ __nv_bfloat16 g_wq[4][CC*CC];     // ternary weights as bf16
__device__ double        g_wpart[4][32];     // partial |W| sums
__device__ float         g_ws_s[4];          // s  = 1/clip(mean,eps)
__device__ float         g_ws_inv[4];        // 1/s = clip(mean,eps)
__device__ float         g_q[MM*CC];         // [B,H,T,hd]
__device__ float         g_k[MM*CC];
__device__ float         g_v[MM*CC];
__device__ float         g_y[MM*CC];         // attention out, [B,T,C]

// ---------------- packed f32x2 helpers (attention) ----------------
#define FMA2(d, a, b) asm volatile("fma.rn.f32x2 %0, %1, %2, %0;" : "+l"(d) : "l"(a), "l"(b))
#define MUL2(d, a)    asm volatile("mul.rn.f32x2 %0, %0, %1;"     : "+l"(d) : "l"(a))
__device__ __forceinline__ unsigned long long pack2(float lo, float hi) {
    unsigned long long r;
    asm("mov.b64 %0, {%1, %2};" : "=l"(r) : "f"(lo), "f"(hi));
    return r;
}
__device__ __forceinline__ void unpack2(unsigned long long v, float& lo, float& hi) {
    asm("mov.b64 {%0, %1}, %2;" : "=f"(lo), "=f"(hi) : "l"(v));
}

// ---------------- cp.async helpers ----------------
__device__ __forceinline__ void cpasync16_s(uint32_t saddr, const void* gmem_ptr) {
    asm volatile("cp.async.cg.shared.global [%0], [%1], 16;\n" :: "r"(saddr), "l"(gmem_ptr));
}
#define CP_COMMIT() asm volatile("cp.async.commit_group;\n")
#define CP_WAIT(N)  asm volatile("cp.async.wait_group %0;\n" :: "n"(N))

// ---------------- weight abs-sum (deterministic, fp64) ----------------
__global__ __launch_bounds__(256) void wsum_kernel(const float* __restrict__ w0,
                                                   const float* __restrict__ w1,
                                                   const float* __restrict__ w2,
                                                   const float* __restrict__ w3)
{
    const float* w = (blockIdx.y == 0) ? w0 : (blockIdx.y == 1) ? w1
                   : (blockIdx.y == 2) ? w2 : w3;
    int base = blockIdx.x * 32768;
    const float4* w4 = (const float4*)(w + base);
    double s = 0.0;
    for (int i = threadIdx.x; i < 8192; i += 256) {
        float4 v = w4[i];
        s += (double)(fabsf(v.x) + fabsf(v.y) + fabsf(v.z) + fabsf(v.w));
    }
    __shared__ double ds[256];
    ds[threadIdx.x] = s;
    __syncthreads();
    for (int st = 128; st; st >>= 1) {
        if (threadIdx.x < st) ds[threadIdx.x] += ds[threadIdx.x + st];
        __syncthreads();
    }
    if (threadIdx.x == 0) g_wpart[blockIdx.y][blockIdx.x] = ds[0];
}

__global__ void wscale_kernel()
{
    int i = threadIdx.x;
    if (i < 4) {
        double s = 0.0;
        for (int j = 0; j < 32; j++) s += g_wpart[i][j];
        float mean = (float)(s / (double)(CC * CC));
        float mc = fmaxf(mean, 1e-5f);
        g_ws_s[i]   = 1.0f / mc;
        g_ws_inv[i] = mc;
    }
}

// ---------------- ternary weight quantization -> bf16 (all 4 weights) ----------------
__global__ __launch_bounds__(256) void wquant_kernel(const float* __restrict__ w0,
                                                     const float* __restrict__ w1,
                                                     const float* __restrict__ w2,
                                                     const float* __restrict__ w3)
{
    int idx = blockIdx.y;
    const float* src = (idx == 0) ? w0 : (idx == 1) ? w1 : (idx == 2) ? w2 : w3;
    float s = g_ws_s[idx];
    int gid = blockIdx.x * 256 + threadIdx.x;        // 1024 blocks -> 262144 float4
    float4 v = ((const float4*)src)[gid];
    float a = fminf(fmaxf(rintf(v.x * s), -1.f), 1.f);
    float b = fminf(fmaxf(rintf(v.y * s), -1.f), 1.f);
    float c = fminf(fmaxf(rintf(v.z * s), -1.f), 1.f);
    float d = fminf(fmaxf(rintf(v.w * s), -1.f), 1.f);
    __nv_bfloat162* out = (__nv_bfloat162*)g_wq[idx];
    out[gid * 2 + 0] = __floats2bfloat162_rn(a, b);
    out[gid * 2 + 1] = __floats2bfloat162_rn(c, d);
}

// ---------------- per-token int8 activation quantization -> bf16 ----------------
__global__ __launch_bounds__(256) void actquant_kernel(const float* __restrict__ xin, int sel)
{
    const float* src      = sel ? (const float*)g_y : xin;
    __nv_bfloat16* outq   = sel ? g_yq : g_xq;
    float* sinv           = sel ? g_ys : g_xs;

    int row = blockIdx.x;
    int tid = threadIdx.x;
    const float4* r4 = (const float4*)(src + (size_t)row * CC);
    float4 v = r4[tid];
    float mx = fmaxf(fmaxf(fabsf(v.x), fabsf(v.y)), fmaxf(fabsf(v.z), fabsf(v.w)));
    for (int o = 16; o; o >>= 1) mx = fmaxf(mx, __shfl_xor_sync(0xffffffffu, mx, o));
    __shared__ float wmax[8];
    if ((tid & 31) == 0) wmax[tid >> 5] = mx;
    __syncthreads();
    float am = wmax[0];
    #pragma unroll
    for (int i = 1; i < 8; i++) am = fmaxf(am, wmax[i]);
    float mc = fmaxf(am, 1e-5f);
    float s = 127.0f / mc;

    float a = fminf(fmaxf(rintf(v.x * s), -128.f), 127.f);
    float b = fminf(fmaxf(rintf(v.y * s), -128.f), 127.f);
    float c = fminf(fmaxf(rintf(v.z * s), -128.f), 127.f);
    float d = fminf(fmaxf(rintf(v.w * s), -128.f), 127.f);
    __nv_bfloat162* o2 = (__nv_bfloat162*)(outq + (size_t)row * CC);
    o2[tid * 2 + 0] = __floats2bfloat162_rn(a, b);
    o2[tid * 2 + 1] = __floats2bfloat162_rn(c, d);
    if (tid == 0) sinv[row] = mc / 127.0f;
}

// ---------------- bf16 MMA GEMM: 4 warps, 64x64 warp tiles, XOR swizzle, 3-stage ----------------
__device__ __forceinline__ void mma16816(float* c, const uint32_t* a, uint32_t b0, uint32_t b1)
{
    asm volatile(
        "mma.sync.aligned.m16n8k16.row.col.f32.bf16.bf16.f32 "
        "{%0,%1,%2,%3}, {%4,%5,%6,%7}, {%8,%9}, {%0,%1,%2,%3};\n"
        : "+f"(c[0]), "+f"(c[1]), "+f"(c[2]), "+f"(c[3])
        : "r"(a[0]), "r"(a[1]), "r"(a[2]), "r"(a[3]), "r"(b0), "r"(b1));
}
__device__ __forceinline__ void ldsm_x4(uint32_t* r, uint32_t addr)
{
    asm volatile("ldmatrix.sync.aligned.m8n8.x4.shared.b16 {%0,%1,%2,%3}, [%4];"
                 : "=r"(r[0]), "=r"(r[1]), "=r"(r[2]), "=r"(r[3]) : "r"(addr));
}

#define BM 128
#define BN 128
#define BK 64                               // halves per stage; 128 bytes/row
#define NSTG 3
#define STAGE_BYTES (128 * 128)             // 16KB per matrix per stage
#define GEMM_SMEM (NSTG * 2 * STAGE_BYTES)  // 98304 bytes

// swizzled byte offset within a tile: row r (0..127), 16B chunk c (0..7)
#define SWZ(r, c) ((uint32_t)((r) * 128 + (((c) ^ ((r) & 7)) << 4)))

__global__ __launch_bounds__(128, 2) void gemm_kernel(int a_sel, int w_idx, int mode,
                                                      float* __restrict__ dst,
                                                      const float* __restrict__ bias)
{
    extern __shared__ __align__(16) char smem[];
    uint32_t sAu = (uint32_t)__cvta_generic_to_shared(smem);
    uint32_t sBu = sAu + NSTG * STAGE_BYTES;

    const __nv_bfloat16* __restrict__ A  = a_sel ? g_xq : g_yq;
    const float* __restrict__ sA         = a_sel ? g_xs : g_ys;
    const __nv_bfloat16* __restrict__ W  = g_wq[w_idx];

    int m0 = blockIdx.x * BM;
    int n0 = blockIdx.y * BN;
    int tid = threadIdx.x;
    int warp = tid >> 5, lane = tid & 31;
    int wm = warp >> 1, wn = warp & 1;     // 2x2 warp grid, warp tile 64x64
    int g = lane >> 2, tg = lane & 3;

    float acc[4][8][4];
    #pragma unroll
    for (int i = 0; i < 4; i++)
        #pragma unroll
        for (int j = 0; j < 8; j++)
            #pragma unroll
            for (int r = 0; r < 4; r++) acc[i][j][r] = 0.f;

    // ldmatrix lane-address components
    int a_r = (lane & 15);            // + wm*64 + mb*16
    int a_c = (lane >> 4);            // chunk offset 0/1
    int b_r = ((lane >> 4) << 3) + (lane & 7);   // + wn*64 + nb*16
    int b_c = ((lane >> 3) & 1);      // chunk offset 0/1

    // stage loader: 1024 chunks of 16B per matrix; 8 per thread per matrix
    auto load_stage = [&](int st, int kk) {
        #pragma unroll
        for (int i = 0; i < 8; i++) {
            int idx = tid + i * 128;           // 0..1023
            int r = idx >> 3, c = idx & 7;
            uint32_t sw = SWZ(r, c);
            cpasync16_s(sAu + st * STAGE_BYTES + sw,
                        &A[(size_t)(m0 + r) * CC + kk + c * 8]);
            cpasync16_s(sBu + st * STAGE_BYTES + sw,
                        &W[(size_t)(n0 + r) * CC + kk + c * 8]);
        }
    };

    load_stage(0, 0);
    CP_COMMIT();
    load_stage(1, BK);
    CP_COMMIT();

    const int NT = CC / BK;   // 16
    for (int t = 0; t < NT; t++) {
        if (t < NT - 1) { CP_WAIT(1); } else { CP_WAIT(0); }
        __syncthreads();

        uint32_t Ab = sAu + (t % NSTG) * STAGE_BYTES;
        uint32_t Bb = sBu + (t % NSTG) * STAGE_BYTES;
        #pragma unroll
        for (int ks = 0; ks < 4; ks++) {       // 4 x k16 per stage
            uint32_t a[4][4], b[4][4];
            #pragma unroll
            for (int mb = 0; mb < 4; mb++) {
                int row = wm * 64 + mb * 16 + a_r;
                ldsm_x4(a[mb], Ab + SWZ(row, ks * 2 + a_c));
            }
            #pragma unroll
            for (int nb = 0; nb < 4; nb++) {
                int row = wn * 64 + nb * 16 + b_r;
                ldsm_x4(b[nb], Bb + SWZ(row, ks * 2 + b_c));
            }
            #pragma unroll
            for (int mb = 0; mb < 4; mb++)
                #pragma unroll
                for (int nb = 0; nb < 4; nb++) {
                    mma16816(acc[mb][2 * nb],     a[mb], b[nb][0], b[nb][1]);
                    mma16816(acc[mb][2 * nb + 1], a[mb], b[nb][2], b[nb][3]);
                }
            if (ks == 0 && t + 2 < NT) {       // overlap next-stage loads with MMA
                load_stage((t + 2) % NSTG, (t + 2) * BK);
                CP_COMMIT();
            }
        }
    }

    // epilogue: scale + write
    float sw = g_ws_inv[w_idx];
    float* sc = (mode == 0) ? g_q : (mode == 1) ? g_k : g_v;   // scatter targets
    #pragma unroll
    for (int i = 0; i < 4; i++) {
        int r0 = m0 + wm * 64 + i * 16 + g;
        float s0 = sA[r0] * sw;
        float s1 = sA[r0 + 8] * sw;
        #pragma unroll
        for (int j = 0; j < 8; j++) {
            int c = n0 + wn * 64 + j * 8 + tg * 2;
            float v00 = acc[i][j][0] * s0, v01 = acc[i][j][1] * s0;
            float v10 = acc[i][j][2] * s1, v11 = acc[i][j][3] * s1;
            if (mode == 3) {
                float b0 = bias[c], b1 = bias[c + 1];
                float2* p0 = (float2*)&dst[(size_t)r0 * CC + c];
                float2* p1 = (float2*)&dst[(size_t)(r0 + 8) * CC + c];
                *p0 = make_float2(v00 + b0, v01 + b1);
                *p1 = make_float2(v10 + b0, v11 + b1);
            } else {
                int h = c >> 6, d = c & 63;
                {
                    int m = r0, t2 = m & (TT - 1), b = m >> 8;
                    float2* p = (float2*)&sc[(((b * HH + h) * TT + t2) * HD) + d];
                    *p = make_float2(v00, v01);
                }
                {
                    int m = r0 + 8, t2 = m & (TT - 1), b = m >> 8;
                    float2* p = (float2*)&sc[(((b * HH + h) * TT + t2) * HD) + d];
                    *p = make_float2(v10, v11);
                }
            }
        }
    }
}

// ---------------- fused causal attention, one (b,h) per CTA, packed f32x2 math ----------------
// smem: K tile [256][64] + V tile [256][64] fp32 = 131072 B (dynamic)
__global__ __launch_bounds__(256) void attn_kernel()
{
    extern __shared__ float smf[];
    float* Ks = smf;
    float* Vs = smf + TT * HD;

    int bh = blockIdx.x;               // 0..1023
    size_t base = (size_t)bh * (TT * HD);
    int tid = threadIdx.x;             // = query row t

    const float4* k4 = (const float4*)(g_k + base);
    const float4* v4 = (const float4*)(g_v + base);
    float4* Ks4 = (float4*)Ks;
    float4* Vs4 = (float4*)Vs;
    #pragma unroll
    for (int i = tid; i < TT * HD / 4; i += 256) {
        Ks4[i] = k4[i];
        Vs4[i] = v4[i];
    }

    unsigned long long q2[32];
    const ulonglong2* qg = (const ulonglong2*)(g_q + base + (size_t)tid * HD);
    #pragma unroll
    for (int i = 0; i < 16; i++) {
        ulonglong2 u = qg[i];
        q2[2 * i] = u.x; q2[2 * i + 1] = u.y;
    }
    __syncthreads();

    float m = -CUDART_INF_F, l = 0.f;
    unsigned long long o2[32];
    #pragma unroll
    for (int i = 0; i < 32; i++) o2[i] = 0ULL;

    for (int j = 0; j <= tid; j++) {
        const ulonglong2* kj = (const ulonglong2*)(Ks + j * HD);   // warp-broadcast
        unsigned long long acc[4] = {0ULL, 0ULL, 0ULL, 0ULL};
        #pragma unroll
        for (int c = 0; c < 16; c++) {
            ulonglong2 kv = kj[c];
            FMA2(acc[c & 3], q2[2 * c],     kv.x);
            FMA2(acc[c & 3], q2[2 * c + 1], kv.y);
        }
        float a0, a1, b0, b1, c0, c1, d0, d1;
        unpack2(acc[0], a0, a1); unpack2(acc[1], b0, b1);
        unpack2(acc[2], c0, c1); unpack2(acc[3], d0, d1);
        float s = (((a0 + a1) + (b0 + b1)) + ((c0 + c1) + (d0 + d1))) * 0.125f; // 1/sqrt(64)

        float p;
        if (s <= m) {
            p = __expf(s - m);
        } else {
            float corr = __expf(m - s);               // exp(-inf)=0 on first iter
            l *= corr;
            unsigned long long corr2 = pack2(corr, corr);
            #pragma unroll
            for (int i = 0; i < 32; i++) MUL2(o2[i], corr2);
            m = s;
            p = 1.f;
        }
        l += p;
        unsigned long long p2 = pack2(p, p);
        const ulonglong2* vj = (const ulonglong2*)(Vs + j * HD);  // warp-broadcast
        #pragma unroll
        for (int c = 0; c < 16; c++) {
            ulonglong2 vv = vj[c];
            FMA2(o2[2 * c],     p2, vv.x);
            FMA2(o2[2 * c + 1], p2, vv.y);
        }
    }

    float inv = 1.0f / l;
    unsigned long long inv2 = pack2(inv, inv);
    int b = bh >> 4, h = bh & (HH - 1);
    unsigned long long* yout =
        (unsigned long long*)(g_y + ((size_t)(b * TT + tid)) * CC + h * HD);
    #pragma unroll
    for (int c = 0; c < 32; c++) {
        MUL2(o2[c], inv2);
        yout[c] = o2[c];
    }
}

// ---------------- launch ----------------
extern "C" void kernel_launch(void* const* d_in, const int* in_sizes, int n_in,
                              void* d_out, int out_size)
{
    const float* x  = (const float*)d_in[0];
    const float* Wq = (const float*)d_in[1];
    const float* Wk = (const float*)d_in[2];
    const float* Wv = (const float*)d_in[3];
    const float* Wp = (const float*)d_in[4];
    const float* bp = (const float*)d_in[5];
    float* out = (float*)d_out;

    cudaFuncSetAttribute(gemm_kernel, cudaFuncAttributeMaxDynamicSharedMemorySize, GEMM_SMEM);
    cudaFuncSetAttribute(attn_kernel, cudaFuncAttributeMaxDynamicSharedMemorySize, 131072);

    // 1) weight scales (deterministic fp64 two-pass)
    wsum_kernel<<<dim3(32, 4), 256>>>(Wq, Wk, Wv, Wp);
    wscale_kernel<<<1, 32>>>();

    // 2) ternary-quantize all 4 weights to bf16 (one launch)
    wquant_kernel<<<dim3(1024, 4), 256>>>(Wq, Wk, Wv, Wp);

    // 3) per-token quantize x
    actquant_kernel<<<MM, 256>>>(x, 0);

    // 4) Q/K/V projections as separate launches (so ncu -s 5 lands on a GEMM)
    dim3 ggrid(MM / BM, CC / BN);
    gemm_kernel<<<ggrid, 128, GEMM_SMEM>>>(1, 0, 0, nullptr, nullptr);
    gemm_kernel<<<ggrid, 128, GEMM_SMEM>>>(1, 1, 1, nullptr, nullptr);
    gemm_kernel<<<ggrid, 128, GEMM_SMEM>>>(1, 2, 2, nullptr, nullptr);

    // 5) fused causal attention
    attn_kernel<<<BB * HH, 256, 131072>>>();

    // 6) quantize attention output
    actquant_kernel<<<MM, 256>>>(nullptr, 1);

    // 7) output projection (+bias) straight into d_out
    gemm_kernel<<<ggrid, 128, GEMM_SMEM>>>(0, 3, 3, out, bp);
}

// round 16
// speedup vs baseline: 1.7854x; 1.0482x over previous
#include <cuda_runtime.h>
#include <cuda_bf16.h>
#include <cstdint>
#include <math_constants.h>

// Problem constants (B=64, T=256, C=1024, H=16, hd=64)
#define BB 64
#define TT 256
#define CC 1024
#define HH 16
#define HD 64
#define MM (BB*TT)   // 16384 rows

// ---------------- static device scratch (no allocation allowed) ----------------
__device__ __nv_bfloat16 g_xq[MM*CC];        // quantized x (int values as bf16)
__device__ float         g_xs[MM];           // per-row 1/s  (= clip(max,eps)/127)
__device__ __nv_bfloat16 g_yq[MM*CC];        // quantized attention output
__device__ float         g_ys[MM];
__device__ __nv_bfloat16 g_wq[4][CC*CC];     // ternary weights as bf16
__device__ double        g_wpart[4][32];     // partial |W| sums
__device__ float         g_ws_s[4];          // s  = 1/clip(mean,eps)
__device__ float         g_ws_inv[4];        // 1/s = clip(mean,eps)
__device__ float         g_q[MM*CC];         // [B,H,T,hd]
__device__ float         g_k[MM*CC];
__device__ float         g_v[MM*CC];
__device__ float         g_y[MM*CC];         // attention out, [B,T,C]

// ---------------- packed f32x2 helpers (attention) ----------------
#define FMA2(d, a, b) asm volatile("fma.rn.f32x2 %0, %1, %2, %0;" : "+l"(d) : "l"(a), "l"(b))
#define MUL2(d, a)    asm volatile("mul.rn.f32x2 %0, %0, %1;"     : "+l"(d) : "l"(a))
__device__ __forceinline__ unsigned long long pack2(float lo, float hi) {
    unsigned long long r;
    asm("mov.b64 %0, {%1, %2};" : "=l"(r) : "f"(lo), "f"(hi));
    return r;
}
__device__ __forceinline__ void unpack2(unsigned long long v, float& lo, float& hi) {
    asm("mov.b64 {%0, %1}, %2;" : "=f"(lo), "=f"(hi) : "l"(v));
}

// ---------------- cp.async helpers ----------------
__device__ __forceinline__ void cpasync16_s(uint32_t saddr, const void* gmem_ptr) {
    asm volatile("cp.async.cg.shared.global [%0], [%1], 16;\n" :: "r"(saddr), "l"(gmem_ptr));
}
#define CP_COMMIT() asm volatile("cp.async.commit_group;\n")
#define CP_WAIT(N)  asm volatile("cp.async.wait_group %0;\n" :: "n"(N))

// ---------------- weight abs-sum (deterministic, fp64) ----------------
__global__ __launch_bounds__(256) void wsum_kernel(const float* __restrict__ w0,
                                                   const float* __restrict__ w1,
                                                   const float* __restrict__ w2,
                                                   const float* __restrict__ w3)
{
    const float* w = (blockIdx.y == 0) ? w0 : (blockIdx.y == 1) ? w1
                   : (blockIdx.y == 2) ? w2 : w3;
    int base = blockIdx.x * 32768;
    const float4* w4 = (const float4*)(w + base);
    double s = 0.0;
    for (int i = threadIdx.x; i < 8192; i += 256) {
        float4 v = w4[i];
        s += (double)(fabsf(v.x) + fabsf(v.y) + fabsf(v.z) + fabsf(v.w));
    }
    __shared__ double ds[256];
    ds[threadIdx.x] = s;
    __syncthreads();
    for (int st = 128; st; st >>= 1) {
        if (threadIdx.x < st) ds[threadIdx.x] += ds[threadIdx.x + st];
        __syncthreads();
    }
    if (threadIdx.x == 0) g_wpart[blockIdx.y][blockIdx.x] = ds[0];
}

__global__ void wscale_kernel()
{
    int i = threadIdx.x;
    if (i < 4) {
        double s = 0.0;
        for (int j = 0; j < 32; j++) s += g_wpart[i][j];
        float mean = (float)(s / (double)(CC * CC));
        float mc = fmaxf(mean, 1e-5f);
        g_ws_s[i]   = 1.0f / mc;
        g_ws_inv[i] = mc;
    }
}

// ---------------- ternary weight quantization -> bf16 (all 4 weights) ----------------
__global__ __launch_bounds__(256) void wquant_kernel(const float* __restrict__ w0,
                                                     const float* __restrict__ w1,
                                                     const float* __restrict__ w2,
                                                     const float* __restrict__ w3)
{
    int idx = blockIdx.y;
    const float* src = (idx == 0) ? w0 : (idx == 1) ? w1 : (idx == 2) ? w2 : w3;
    float s = g_ws_s[idx];
    int gid = blockIdx.x * 256 + threadIdx.x;        // 1024 blocks -> 262144 float4
    float4 v = ((const float4*)src)[gid];
    float a = fminf(fmaxf(rintf(v.x * s), -1.f), 1.f);
    float b = fminf(fmaxf(rintf(v.y * s), -1.f), 1.f);
    float c = fminf(fmaxf(rintf(v.z * s), -1.f), 1.f);
    float d = fminf(fmaxf(rintf(v.w * s), -1.f), 1.f);
    __nv_bfloat162* out = (__nv_bfloat162*)g_wq[idx];
    out[gid * 2 + 0] = __floats2bfloat162_rn(a, b);
    out[gid * 2 + 1] = __floats2bfloat162_rn(c, d);
}

// ---------------- per-token int8 activation quantization -> bf16 ----------------
__global__ __launch_bounds__(256) void actquant_kernel(const float* __restrict__ xin, int sel)
{
    const float* src      = sel ? (const float*)g_y : xin;
    __nv_bfloat16* outq   = sel ? g_yq : g_xq;
    float* sinv           = sel ? g_ys : g_xs;

    int row = blockIdx.x;
    int tid = threadIdx.x;
    const float4* r4 = (const float4*)(src + (size_t)row * CC);
    float4 v = r4[tid];
    float mx = fmaxf(fmaxf(fabsf(v.x), fabsf(v.y)), fmaxf(fabsf(v.z), fabsf(v.w)));
    for (int o = 16; o; o >>= 1) mx = fmaxf(mx, __shfl_xor_sync(0xffffffffu, mx, o));
    __shared__ float wmax[8];
    if ((tid & 31) == 0) wmax[tid >> 5] = mx;
    __syncthreads();
    float am = wmax[0];
    #pragma unroll
    for (int i = 1; i < 8; i++) am = fmaxf(am, wmax[i]);
    float mc = fmaxf(am, 1e-5f);
    float s = 127.0f / mc;

    float a = fminf(fmaxf(rintf(v.x * s), -128.f), 127.f);
    float b = fminf(fmaxf(rintf(v.y * s), -128.f), 127.f);
    float c = fminf(fmaxf(rintf(v.z * s), -128.f), 127.f);
    float d = fminf(fmaxf(rintf(v.w * s), -128.f), 127.f);
    __nv_bfloat162* o2 = (__nv_bfloat162*)(outq + (size_t)row * CC);
    o2[tid * 2 + 0] = __floats2bfloat162_rn(a, b);
    o2[tid * 2 + 1] = __floats2bfloat162_rn(c, d);
    if (tid == 0) sinv[row] = mc / 127.0f;
}

// ---------------- bf16 MMA GEMM: 4 warps, 64x64 warp tiles, XOR swizzle, 3-stage ----------------
__device__ __forceinline__ void mma16816(float* c, const uint32_t* a, uint32_t b0, uint32_t b1)
{
    asm volatile(
        "mma.sync.aligned.m16n8k16.row.col.f32.bf16.bf16.f32 "
        "{%0,%1,%2,%3}, {%4,%5,%6,%7}, {%8,%9}, {%0,%1,%2,%3};\n"
        : "+f"(c[0]), "+f"(c[1]), "+f"(c[2]), "+f"(c[3])
        : "r"(a[0]), "r"(a[1]), "r"(a[2]), "r"(a[3]), "r"(b0), "r"(b1));
}
__device__ __forceinline__ void ldsm_x4(uint32_t* r, uint32_t addr)
{
    asm volatile("ldmatrix.sync.aligned.m8n8.x4.shared.b16 {%0,%1,%2,%3}, [%4];"
                 : "=r"(r[0]), "=r"(r[1]), "=r"(r[2]), "=r"(r[3]) : "r"(addr));
}

#define BM 128
#define BN 128
#define BK 64                               // halves per stage; 128 bytes/row
#define NSTG 3
#define STAGE_BYTES (128 * 128)             // 16KB per matrix per stage
#define GEMM_SMEM (NSTG * 2 * STAGE_BYTES)  // 98304 bytes

// swizzled byte offset within a tile: row r (0..127), 16B chunk c (0..7)
#define SWZ(r, c) ((uint32_t)((r) * 128 + (((c) ^ ((r) & 7)) << 4)))

__global__ __launch_bounds__(128, 2) void gemm_kernel(int qkv, int w_idx_p, int mode_p,
                                                      float* __restrict__ dst,
                                                      const float* __restrict__ bias)
{
    extern __shared__ __align__(16) char smem[];
    uint32_t sAu = (uint32_t)__cvta_generic_to_shared(smem);
    uint32_t sBu = sAu + NSTG * STAGE_BYTES;

    int w_idx = qkv ? (int)blockIdx.z : w_idx_p;
    int mode  = qkv ? (int)blockIdx.z : mode_p;

    const __nv_bfloat16* __restrict__ A  = qkv ? g_xq : g_yq;
    const float* __restrict__ sA         = qkv ? g_xs : g_ys;
    const __nv_bfloat16* __restrict__ W  = g_wq[w_idx];

    int m0 = blockIdx.x * BM;
    int n0 = blockIdx.y * BN;
    int tid = threadIdx.x;
    int warp = tid >> 5, lane = tid & 31;
    int wm = warp >> 1, wn = warp & 1;     // 2x2 warp grid, warp tile 64x64
    int g = lane >> 2, tg = lane & 3;

    float acc[4][8][4];
    #pragma unroll
    for (int i = 0; i < 4; i++)
        #pragma unroll
        for (int j = 0; j < 8; j++)
            #pragma unroll
            for (int r = 0; r < 4; r++) acc[i][j][r] = 0.f;

    // ldmatrix lane-address components
    int a_r = (lane & 15);            // + wm*64 + mb*16
    int a_c = (lane >> 4);            // chunk offset 0/1
    int b_r = ((lane >> 4) << 3) + (lane & 7);   // + wn*64 + nb*16
    int b_c = ((lane >> 3) & 1);      // chunk offset 0/1

    // stage loader: 1024 chunks of 16B per matrix; 8 per thread per matrix
    auto load_stage = [&](int st, int kk) {
        #pragma unroll
        for (int i = 0; i < 8; i++) {
            int idx = tid + i * 128;           // 0..1023
            int r = idx >> 3, c = idx & 7;
            uint32_t sw = SWZ(r, c);
            cpasync16_s(sAu + st * STAGE_BYTES + sw,
                        &A[(size_t)(m0 + r) * CC + kk + c * 8]);
            cpasync16_s(sBu + st * STAGE_BYTES + sw,
                        &W[(size_t)(n0 + r) * CC + kk + c * 8]);
        }
    };

    load_stage(0, 0);
    CP_COMMIT();
    load_stage(1, BK);
    CP_COMMIT();

    const int NT = CC / BK;   // 16
    for (int t = 0; t < NT; t++) {
        if (t < NT - 1) { CP_WAIT(1); } else { CP_WAIT(0); }
        __syncthreads();

        uint32_t Ab = sAu + (t % NSTG) * STAGE_BYTES;
        uint32_t Bb = sBu + (t % NSTG) * STAGE_BYTES;
        #pragma unroll
        for (int ks = 0; ks < 4; ks++) {       // 4 x k16 per stage
            uint32_t a[4][4], b[4][4];
            #pragma unroll
            for (int mb = 0; mb < 4; mb++) {
                int row = wm * 64 + mb * 16 + a_r;
                ldsm_x4(a[mb], Ab + SWZ(row, ks * 2 + a_c));
            }
            #pragma unroll
            for (int nb = 0; nb < 4; nb++) {
                int row = wn * 64 + nb * 16 + b_r;
                ldsm_x4(b[nb], Bb + SWZ(row, ks * 2 + b_c));
            }
            #pragma unroll
            for (int mb = 0; mb < 4; mb++)
                #pragma unroll
                for (int nb = 0; nb < 4; nb++) {
                    mma16816(acc[mb][2 * nb],     a[mb], b[nb][0], b[nb][1]);
                    mma16816(acc[mb][2 * nb + 1], a[mb], b[nb][2], b[nb][3]);
                }
            if (ks == 0 && t + 2 < NT) {       // overlap next-stage loads with MMA
                load_stage((t + 2) % NSTG, (t + 2) * BK);
                CP_COMMIT();
            }
        }
    }

    // epilogue: scale + write
    float sw = g_ws_inv[w_idx];
    float* sc = (mode == 0) ? g_q : (mode == 1) ? g_k : g_v;   // scatter targets
    #pragma unroll
    for (int i = 0; i < 4; i++) {
        int r0 = m0 + wm * 64 + i * 16 + g;
        float s0 = sA[r0] * sw;
        float s1 = sA[r0 + 8] * sw;
        #pragma unroll
        for (int j = 0; j < 8; j++) {
            int c = n0 + wn * 64 + j * 8 + tg * 2;
            float v00 = acc[i][j][0] * s0, v01 = acc[i][j][1] * s0;
            float v10 = acc[i][j][2] * s1, v11 = acc[i][j][3] * s1;
            if (mode == 3) {
                float b0 = bias[c], b1 = bias[c + 1];
                float2* p0 = (float2*)&dst[(size_t)r0 * CC + c];
                float2* p1 = (float2*)&dst[(size_t)(r0 + 8) * CC + c];
                *p0 = make_float2(v00 + b0, v01 + b1);
                *p1 = make_float2(v10 + b0, v11 + b1);
            } else {
                int h = c >> 6, d = c & 63;
                {
                    int m = r0, t2 = m & (TT - 1), b = m >> 8;
                    float2* p = (float2*)&sc[(((b * HH + h) * TT + t2) * HD) + d];
                    *p = make_float2(v00, v01);
                }
                {
                    int m = r0 + 8, t2 = m & (TT - 1), b = m >> 8;
                    float2* p = (float2*)&sc[(((b * HH + h) * TT + t2) * HD) + d];
                    *p = make_float2(v10, v11);
                }
            }
        }
    }
}

// ---------------- fused causal attention, one (b,h) per CTA, packed f32x2 math ----------------
// SMSP-balanced: warp w handles row block PERM[w] so each SMSP (warps s, s+4)
// gets blocks s and 7-s -> equal causal work (286 warp-iters) on all 4 SMSPs.
// smem: K tile [256][64] + V tile [256][64] fp32 = 131072 B (dynamic)
__constant__ int c_perm[8] = {0, 1, 2, 3, 7, 6, 5, 4};

__global__ __launch_bounds__(256) void attn_kernel()
{
    extern __shared__ float smf[];
    float* Ks = smf;
    float* Vs = smf + TT * HD;

    int bh = blockIdx.x;               // 0..1023
    size_t base = (size_t)bh * (TT * HD);
    int tid = threadIdx.x;
    int row = c_perm[tid >> 5] * 32 + (tid & 31);   // balanced query row

    const float4* k4 = (const float4*)(g_k + base);
    const float4* v4 = (const float4*)(g_v + base);
    float4* Ks4 = (float4*)Ks;
    float4* Vs4 = (float4*)Vs;
    #pragma unroll
    for (int i = tid; i < TT * HD / 4; i += 256) {
        Ks4[i] = k4[i];
        Vs4[i] = v4[i];
    }

    unsigned long long q2[32];
    const ulonglong2* qg = (const ulonglong2*)(g_q + base + (size_t)row * HD);
    #pragma unroll
    for (int i = 0; i < 16; i++) {
        ulonglong2 u = qg[i];
        q2[2 * i] = u.x; q2[2 * i + 1] = u.y;
    }
    __syncthreads();

    float m = -CUDART_INF_F, l = 0.f;
    unsigned long long o2[32];
    #pragma unroll
    for (int i = 0; i < 32; i++) o2[i] = 0ULL;

    for (int j = 0; j <= row; j++) {
        const ulonglong2* kj = (const ulonglong2*)(Ks + j * HD);   // warp-broadcast
        unsigned long long acc[4] = {0ULL, 0ULL, 0ULL, 0ULL};
        #pragma unroll
        for (int c = 0; c < 16; c++) {
            ulonglong2 kv = kj[c];
            FMA2(acc[c & 3], q2[2 * c],     kv.x);
            FMA2(acc[c & 3], q2[2 * c + 1], kv.y);
        }
        float a0, a1, b0, b1, c0, c1, d0, d1;
        unpack2(acc[0], a0, a1); unpack2(acc[1], b0, b1);
        unpack2(acc[2], c0, c1); unpack2(acc[3], d0, d1);
        float s = (((a0 + a1) + (b0 + b1)) + ((c0 + c1) + (d0 + d1))) * 0.125f; // 1/sqrt(64)

        float p;
        if (s <= m) {
            p = __expf(s - m);
        } else {
            float corr = __expf(m - s);               // exp(-inf)=0 on first iter
            l *= corr;
            unsigned long long corr2 = pack2(corr, corr);
            #pragma unroll
            for (int i = 0; i < 32; i++) MUL2(o2[i], corr2);
            m = s;
            p = 1.f;
        }
        l += p;
        unsigned long long p2 = pack2(p, p);
        const ulonglong2* vj = (const ulonglong2*)(Vs + j * HD);  // warp-broadcast
        #pragma unroll
        for (int c = 0; c < 16; c++) {
            ulonglong2 vv = vj[c];
            FMA2(o2[2 * c],     p2, vv.x);
            FMA2(o2[2 * c + 1], p2, vv.y);
        }
    }

    float inv = 1.0f / l;
    unsigned long long inv2 = pack2(inv, inv);
    int b = bh >> 4, h = bh & (HH - 1);
    unsigned long long* yout =
        (unsigned long long*)(g_y + ((size_t)(b * TT + row)) * CC + h * HD);
    #pragma unroll
    for (int c = 0; c < 32; c++) {
        MUL2(o2[c], inv2);
        yout[c] = o2[c];
    }
}

// ---------------- launch ----------------
extern "C" void kernel_launch(void* const* d_in, const int* in_sizes, int n_in,
                              void* d_out, int out_size)
{
    const float* x  = (const float*)d_in[0];
    const float* Wq = (const float*)d_in[1];
    const float* Wk = (const float*)d_in[2];
    const float* Wv = (const float*)d_in[3];
    const float* Wp = (const float*)d_in[4];
    const float* bp = (const float*)d_in[5];
    float* out = (float*)d_out;

    cudaFuncSetAttribute(gemm_kernel, cudaFuncAttributeMaxDynamicSharedMemorySize, GEMM_SMEM);
    cudaFuncSetAttribute(attn_kernel, cudaFuncAttributeMaxDynamicSharedMemorySize, 131072);

    // 1) weight scales (deterministic fp64 two-pass)
    wsum_kernel<<<dim3(32, 4), 256>>>(Wq, Wk, Wv, Wp);
    wscale_kernel<<<1, 32>>>();

    // 2) ternary-quantize all 4 weights to bf16 (one launch)
    wquant_kernel<<<dim3(1024, 4), 256>>>(Wq, Wk, Wv, Wp);

    // 3) per-token quantize x
    actquant_kernel<<<MM, 256>>>(x, 0);

    // 4) Q/K/V projections fused in one z=3 launch (less wave-tail waste)
    gemm_kernel<<<dim3(MM / BM, CC / BN, 3), 128, GEMM_SMEM>>>(1, 0, 0, nullptr, nullptr);

    // 5) fused causal attention (SMSP-balanced)
    attn_kernel<<<BB * HH, 256, 131072>>>();

    // 6) quantize attention output
    actquant_kernel<<<MM, 256>>>(nullptr, 1);

    // 7) output projection (+bias) straight into d_out
    gemm_kernel<<<dim3(MM / BM, CC / BN, 1), 128, GEMM_SMEM>>>(0, 3, 3, out, bp);
}